// round 1
// baseline (speedup 1.0000x reference)
#include <cuda_runtime.h>
#include <math.h>

#define BATCH   2
#define SEQLEN  2048
#define NTOK    (BATCH*SEQLEN)        // 4096
#define DMODEL  768
#define DINNER  1536
#define DSTATE  128
#define HEADDIM 64
#define NHEADS  24
#define CONVDIM 1792                  // DINNER + 2*DSTATE
#define DINPROJ 3352                  // 2*DINNER + 2*DSTATE + NHEADS

// ---------------------------------------------------------------------------
// Scratch buffers (device globals — no allocations allowed)
// ---------------------------------------------------------------------------
__device__ __align__(128) float g_zx[NTOK * DINPROJ];     // in_proj output
__device__ __align__(128) float g_conv[NTOK * CONVDIM];   // conv+silu output (x | B | C)
__device__ __align__(128) float g_dt[NTOK * NHEADS];      // softplus(dt + bias)
__device__ __align__(128) float g_dA[NTOK * NHEADS];      // exp(dt * A)
__device__ __align__(128) float g_y[NTOK * DINNER];       // scan output (atomics)
__device__ __align__(128) float g_yn[NTOK * DINNER];      // gated + rmsnormed

// ---------------------------------------------------------------------------
// SGEMM: C[M,N] = A[M,K] * B[N,K]^T   (both row-major; B is a weight matrix)
// 128x128 tile, BK=8, 256 threads, 8x8 per thread. M % 128 == 0, K % 8 == 0.
// ---------------------------------------------------------------------------
__global__ __launch_bounds__(256) void sgemm_nt(
    const float* __restrict__ A, const float* __restrict__ Bw,
    float* __restrict__ C, int M, int N, int K)
{
    __shared__ float As[8][128];
    __shared__ float Bs[8][128];
    const int bm = blockIdx.y * 128;
    const int bn = blockIdx.x * 128;
    const int tid  = threadIdx.x;
    const int trow = tid >> 4;        // 0..15
    const int tcol = tid & 15;        // 0..15
    const int lrow = tid >> 1;        // 0..127
    const int lcol = (tid & 1) << 2;  // 0 or 4

    float acc[8][8];
#pragma unroll
    for (int i = 0; i < 8; i++)
#pragma unroll
        for (int j = 0; j < 8; j++) acc[i][j] = 0.f;

    const float* Aptr = A  + (size_t)(bm + lrow) * K + lcol;
    const float* Bptr = Bw + (size_t)(bn + lrow) * K + lcol;
    const bool bvalid = (bn + lrow) < N;

    for (int k0 = 0; k0 < K; k0 += 8) {
        float4 av = *(const float4*)(Aptr + k0);
        float4 bv = make_float4(0.f, 0.f, 0.f, 0.f);
        if (bvalid) bv = *(const float4*)(Bptr + k0);
        __syncthreads();
        As[lcol + 0][lrow] = av.x; As[lcol + 1][lrow] = av.y;
        As[lcol + 2][lrow] = av.z; As[lcol + 3][lrow] = av.w;
        Bs[lcol + 0][lrow] = bv.x; Bs[lcol + 1][lrow] = bv.y;
        Bs[lcol + 2][lrow] = bv.z; Bs[lcol + 3][lrow] = bv.w;
        __syncthreads();
#pragma unroll
        for (int k = 0; k < 8; k++) {
            float ar[8], br[8];
#pragma unroll
            for (int i = 0; i < 8; i++) ar[i] = As[k][trow * 8 + i];
#pragma unroll
            for (int j = 0; j < 8; j++) br[j] = Bs[k][tcol * 8 + j];
#pragma unroll
            for (int i = 0; i < 8; i++)
#pragma unroll
                for (int j = 0; j < 8; j++)
                    acc[i][j] = fmaf(ar[i], br[j], acc[i][j]);
        }
    }
#pragma unroll
    for (int i = 0; i < 8; i++) {
        const int gm = bm + trow * 8 + i;
#pragma unroll
        for (int j = 0; j < 8; j++) {
            const int gn = bn + tcol * 8 + j;
            if (gn < N) C[(size_t)gm * N + gn] = acc[i][j];
        }
    }
}

// ---------------------------------------------------------------------------
// Depthwise causal conv (width 4) + bias + SiLU over the xBC slice of g_zx.
// ---------------------------------------------------------------------------
__global__ void conv_silu_kernel(const float* __restrict__ cw,
                                 const float* __restrict__ cb)
{
    const int idx = blockIdx.x * 256 + threadIdx.x;
    if (idx >= NTOK * CONVDIM) return;
    const int c  = idx % CONVDIM;
    const int bt = idx / CONVDIM;
    const int t  = bt % SEQLEN;
    float acc = cb[c];
#pragma unroll
    for (int k = 0; k < 4; k++) {
        const int tt = t - 3 + k;
        if (tt >= 0)
            acc = fmaf(cw[c * 4 + k],
                       g_zx[((size_t)bt + k - 3) * DINPROJ + DINNER + c], acc);
    }
    g_conv[idx] = acc / (1.f + expf(-acc));   // silu
}

// ---------------------------------------------------------------------------
// dt_dis = softplus(dt + dt_bias); dA = exp(dt_dis * (-exp(A_log)))
// ---------------------------------------------------------------------------
__global__ void dt_kernel(const float* __restrict__ dt_bias,
                          const float* __restrict__ A_log)
{
    const int idx = blockIdx.x * 256 + threadIdx.x;
    if (idx >= NTOK * NHEADS) return;
    const int h  = idx % NHEADS;
    const int bt = idx / NHEADS;
    const float x  = g_zx[(size_t)bt * DINPROJ + DINNER + CONVDIM + h] + dt_bias[h];
    const float sp = (x > 20.f) ? x : log1pf(expf(x));
    const float Ah = -expf(A_log[h]);
    g_dt[idx] = sp;
    g_dA[idx] = expf(sp * Ah);
}

__global__ void zero_y_kernel()
{
    const int idx = blockIdx.x * 256 + threadIdx.x;
    if (idx < NTOK * DINNER) g_y[idx] = 0.f;
}

// ---------------------------------------------------------------------------
// Selective scan. grid = (4 n-slices, NHEADS, BATCH), 256 threads.
// thread (p = tid>>2, q = tid&3) owns state[p, nb..nb+8) in registers.
// 1-step lookahead loads hide L2 latency; no smem, no barriers.
// ---------------------------------------------------------------------------
__global__ __launch_bounds__(256) void scan_kernel()
{
    const int g4 = blockIdx.x, h = blockIdx.y, b = blockIdx.z;
    const int tid = threadIdx.x;
    const int p = tid >> 2, q = tid & 3;
    const int nb = g4 * 32 + q * 8;

    const float* rowbase = g_conv + (size_t)b * SEQLEN * CONVDIM;
    const float* dtp = g_dt + (size_t)b * SEQLEN * NHEADS + h;
    const float* dAp = g_dA + (size_t)b * SEQLEN * NHEADS + h;
    float* yout = g_y + (size_t)b * SEQLEN * DINNER + h * HEADDIM + p;

    float s[8];
#pragma unroll
    for (int i = 0; i < 8; i++) s[i] = 0.f;

    // preload t = 0
    const float* r0 = rowbase;
    float4 nB0 = *(const float4*)(r0 + DINNER + nb);
    float4 nB1 = *(const float4*)(r0 + DINNER + nb + 4);
    float4 nC0 = *(const float4*)(r0 + DINNER + DSTATE + nb);
    float4 nC1 = *(const float4*)(r0 + DINNER + DSTATE + nb + 4);
    float nx  = r0[h * HEADDIM + p];
    float ndt = dtp[0];
    float ndA = dAp[0];

    for (int t = 0; t < SEQLEN; ++t) {
        const float4 B0 = nB0, B1 = nB1, C0 = nC0, C1 = nC1;
        const float xv = nx, dtv = ndt, dAv = ndA;
        if (t + 1 < SEQLEN) {
            const float* r = rowbase + (size_t)(t + 1) * CONVDIM;
            nB0 = *(const float4*)(r + DINNER + nb);
            nB1 = *(const float4*)(r + DINNER + nb + 4);
            nC0 = *(const float4*)(r + DINNER + DSTATE + nb);
            nC1 = *(const float4*)(r + DINNER + DSTATE + nb + 4);
            nx  = r[h * HEADDIM + p];
            ndt = dtp[(size_t)(t + 1) * NHEADS];
            ndA = dAp[(size_t)(t + 1) * NHEADS];
        }
        const float coef = dtv * xv;
        float acc;
        s[0] = fmaf(s[0], dAv, coef * B0.x); acc = s[0] * C0.x;
        s[1] = fmaf(s[1], dAv, coef * B0.y); acc = fmaf(s[1], C0.y, acc);
        s[2] = fmaf(s[2], dAv, coef * B0.z); acc = fmaf(s[2], C0.z, acc);
        s[3] = fmaf(s[3], dAv, coef * B0.w); acc = fmaf(s[3], C0.w, acc);
        s[4] = fmaf(s[4], dAv, coef * B1.x); acc = fmaf(s[4], C1.x, acc);
        s[5] = fmaf(s[5], dAv, coef * B1.y); acc = fmaf(s[5], C1.y, acc);
        s[6] = fmaf(s[6], dAv, coef * B1.z); acc = fmaf(s[6], C1.z, acc);
        s[7] = fmaf(s[7], dAv, coef * B1.w); acc = fmaf(s[7], C1.w, acc);
        // sum over the 4 n-subslices held by lanes differing in bits 0..1
        acc += __shfl_xor_sync(0xffffffffu, acc, 1);
        acc += __shfl_xor_sync(0xffffffffu, acc, 2);
        if (q == 0) atomicAdd(yout + (size_t)t * DINNER, acc);
    }
}

// ---------------------------------------------------------------------------
// y += x*D; yz = y*silu(z); RMSNorm(yz) * norm_w  -> g_yn. One block / token.
// ---------------------------------------------------------------------------
__global__ __launch_bounds__(256) void gate_norm_kernel(
    const float* __restrict__ Dv, const float* __restrict__ nw)
{
    const int bt = blockIdx.x;
    const float* zrow = g_zx   + (size_t)bt * DINPROJ;
    const float* xrow = g_conv + (size_t)bt * CONVDIM;
    const float* yrow = g_y    + (size_t)bt * DINNER;

    float v[6];
    float ss = 0.f;
#pragma unroll
    for (int i = 0; i < 6; i++) {
        const int c = threadIdx.x + i * 256;
        const float yv = fmaf(xrow[c], Dv[c >> 6], yrow[c]);
        const float z  = zrow[c];
        const float gz = z / (1.f + expf(-z));
        const float val = yv * gz;
        v[i] = val;
        ss = fmaf(val, val, ss);
    }
#pragma unroll
    for (int o = 16; o; o >>= 1) ss += __shfl_xor_sync(0xffffffffu, ss, o);
    __shared__ float sred[8];
    if ((threadIdx.x & 31) == 0) sred[threadIdx.x >> 5] = ss;
    __syncthreads();
    float tot = 0.f;
#pragma unroll
    for (int i = 0; i < 8; i++) tot += sred[i];
    const float scale = rsqrtf(tot * (1.f / DINNER) + 1e-5f);

    float* yn = g_yn + (size_t)bt * DINNER;
#pragma unroll
    for (int i = 0; i < 6; i++) {
        const int c = threadIdx.x + i * 256;
        yn[c] = v[i] * scale * nw[c];
    }
}

// ---------------------------------------------------------------------------
// Launch
// ---------------------------------------------------------------------------
extern "C" void kernel_launch(void* const* d_in, const int* in_sizes, int n_in,
                              void* d_out, int out_size)
{
    const float* u          = (const float*)d_in[0];
    const float* in_proj_w  = (const float*)d_in[1];
    const float* conv_w     = (const float*)d_in[2];
    const float* conv_b     = (const float*)d_in[3];
    const float* dt_bias    = (const float*)d_in[4];
    const float* A_log      = (const float*)d_in[5];
    const float* Dv         = (const float*)d_in[6];
    const float* norm_w     = (const float*)d_in[7];
    const float* out_proj_w = (const float*)d_in[8];
    float* out = (float*)d_out;

    float *zx = nullptr, *yn = nullptr;
    cudaGetSymbolAddress((void**)&zx, g_zx);
    cudaGetSymbolAddress((void**)&yn, g_yn);

    // 1) zxbcdt = u @ in_proj_w^T   (4096 x 3352, K=768)
    dim3 g1((DINPROJ + 127) / 128, NTOK / 128);
    sgemm_nt<<<g1, 256>>>(u, in_proj_w, zx, NTOK, DINPROJ, DMODEL);

    // 2) depthwise causal conv + silu on xBC slice
    conv_silu_kernel<<<(NTOK * CONVDIM + 255) / 256, 256>>>(conv_w, conv_b);

    // 3) dt softplus / dA
    dt_kernel<<<(NTOK * NHEADS + 255) / 256, 256>>>(dt_bias, A_log);

    // 4) zero scan accumulator
    zero_y_kernel<<<(NTOK * DINNER + 255) / 256, 256>>>();

    // 5) selective scan
    scan_kernel<<<dim3(4, NHEADS, BATCH), 256>>>();

    // 6) gate + RMSNorm
    gate_norm_kernel<<<NTOK, 256>>>(Dv, norm_w);

    // 7) out = yn @ out_proj_w^T   (4096 x 768, K=1536)
    dim3 g2((DMODEL + 127) / 128, NTOK / 128);
    sgemm_nt<<<g2, 256>>>(yn, out_proj_w, out, NTOK, DMODEL, DINNER);
}

// round 3
// speedup vs baseline: 1.5641x; 1.5641x over previous
#include <cuda_runtime.h>
#include <cuda_bf16.h>
#include <math.h>
#include <stdint.h>

#define BATCH   2
#define SEQLEN  2048
#define NTOK    (BATCH*SEQLEN)        // 4096
#define DMODEL  768
#define DINNER  1536
#define DSTATE  128
#define HEADDIM 64
#define NHEADS  24
#define CONVDIM 1792                  // DINNER + 2*DSTATE
#define DINPROJ 3352                  // 2*DINNER + 2*DSTATE + NHEADS

// ---------------------------------------------------------------------------
// Scratch buffers (device globals — no allocations allowed)
// ---------------------------------------------------------------------------
__device__ __align__(128) float g_zx[NTOK * DINPROJ];     // in_proj output
__device__ __align__(128) float g_conv[NTOK * CONVDIM];   // conv+silu output (x | B | C)
__device__ __align__(128) float g_dt[NTOK * NHEADS];      // softplus(dt + bias)
__device__ __align__(128) float g_dA[NTOK * NHEADS];      // exp(dt * A)
__device__ __align__(128) float g_y[NTOK * DINNER];       // scan output (atomics)

// bf16 hi/lo split operands for tensor-core GEMMs
__device__ __align__(128) __nv_bfloat16 g_u_hi[NTOK * DMODEL];
__device__ __align__(128) __nv_bfloat16 g_u_lo[NTOK * DMODEL];
__device__ __align__(128) __nv_bfloat16 g_w1_hi[DINPROJ * DMODEL];
__device__ __align__(128) __nv_bfloat16 g_w1_lo[DINPROJ * DMODEL];
__device__ __align__(128) __nv_bfloat16 g_w2_hi[DMODEL * DINNER];
__device__ __align__(128) __nv_bfloat16 g_w2_lo[DMODEL * DINNER];
__device__ __align__(128) __nv_bfloat16 g_yn_hi[NTOK * DINNER];
__device__ __align__(128) __nv_bfloat16 g_yn_lo[NTOK * DINNER];

// ---------------------------------------------------------------------------
// MMA helpers (baseline PTX — works under compute_103 virtual arch)
// ---------------------------------------------------------------------------
static __device__ __forceinline__ uint32_t smem_u32(const void* p) {
    return (uint32_t)__cvta_generic_to_shared(p);
}

static __device__ __forceinline__ void mma_bf16(
    float* d, const uint32_t* a, const uint32_t* b)
{
    asm volatile(
        "mma.sync.aligned.m16n8k16.row.col.f32.bf16.bf16.f32 "
        "{%0,%1,%2,%3}, {%4,%5,%6,%7}, {%8,%9}, {%0,%1,%2,%3};"
        : "+f"(d[0]), "+f"(d[1]), "+f"(d[2]), "+f"(d[3])
        : "r"(a[0]), "r"(a[1]), "r"(a[2]), "r"(a[3]), "r"(b[0]), "r"(b[1]));
}

static __device__ __forceinline__ void ldmatrix_x4(uint32_t* r, uint32_t addr)
{
    asm volatile("ldmatrix.sync.aligned.m8n8.x4.shared.b16 {%0,%1,%2,%3}, [%4];"
                 : "=r"(r[0]), "=r"(r[1]), "=r"(r[2]), "=r"(r[3]) : "r"(addr));
}

static __device__ __forceinline__ void ldmatrix_x2(uint32_t* r, uint32_t addr)
{
    asm volatile("ldmatrix.sync.aligned.m8n8.x2.shared.b16 {%0,%1}, [%2];"
                 : "=r"(r[0]), "=r"(r[1]) : "r"(addr));
}

static __device__ __forceinline__ void cp16(uint32_t dst, const void* src, int sz)
{
    asm volatile("cp.async.cg.shared.global [%0], [%1], 16, %2;"
                 :: "r"(dst), "l"(src), "r"(sz));
}

// ---------------------------------------------------------------------------
// bf16x3 GEMM via mma.sync:  C[M,N] = A[M,K] @ B[N,K]^T  (~fp32 accuracy)
// CTA tile 128x128, BK=32, 8 warps (2x4), warp tile 64x32.
// Double-buffered cp.async staging; 80B-padded rows -> conflict-free ldmatrix.
// M % 128 == 0, K % 32 == 0; N guarded.
// ---------------------------------------------------------------------------
#define ROWB   80                         // padded row stride (32 bf16 -> 80B)
#define MATB   (128 * ROWB)               // 10240 per matrix
#define STAGEB (4 * MATB)                 // Ah | Al | Bh | Bl  = 40960
#define GEMM_SMEM (2 * STAGEB)            // 81920

__global__ void __launch_bounds__(256) gemm_mma(
    const __nv_bfloat16* __restrict__ Ah, const __nv_bfloat16* __restrict__ Al,
    const __nv_bfloat16* __restrict__ Bh, const __nv_bfloat16* __restrict__ Bl,
    float* __restrict__ C, int M, int N, int K)
{
    extern __shared__ __align__(128) char smem[];
    const uint32_t sb = smem_u32(smem);
    const int tid = threadIdx.x;
    const int wid = tid >> 5, lid = tid & 31;
    const int bm = blockIdx.y * 128;
    const int bn = blockIdx.x * 128;
    const int wr = wid & 1;               // warp m-row (x64)
    const int wc = wid >> 1;              // warp n-col (x32)

    float acc[4][4][4];
#pragma unroll
    for (int i = 0; i < 4; i++)
#pragma unroll
        for (int j = 0; j < 4; j++)
#pragma unroll
            for (int k = 0; k < 4; k++) acc[i][j][k] = 0.f;

    // staging: thread -> (row = tid>>1, two 16B chunks at (tid&1)*2)
    const int lrow = tid >> 1;
    const int lch  = (tid & 1) * 2;
    const int bok  = (bn + lrow) < N ? 16 : 0;
    const size_t arowoff = (size_t)(bm + lrow) * K;
    const size_t browoff = (size_t)(bok ? (bn + lrow) : 0) * K;
    const uint32_t dst0 = sb + lrow * ROWB + lch * 16;

    const int NC = K >> 5;

    // prologue: stage chunk 0 into stage 0
    {
        const size_t ao = arowoff + lch * 8;
        const size_t bo = browoff + lch * 8;
        cp16(dst0,             Ah + ao, 16); cp16(dst0 + 16,            Ah + ao + 8, 16);
        cp16(dst0 + MATB,      Al + ao, 16); cp16(dst0 + MATB + 16,     Al + ao + 8, 16);
        cp16(dst0 + 2*MATB,    Bh + bo, bok); cp16(dst0 + 2*MATB + 16,  Bh + bo + 8, bok);
        cp16(dst0 + 3*MATB,    Bl + bo, bok); cp16(dst0 + 3*MATB + 16,  Bl + bo + 8, bok);
        asm volatile("cp.async.commit_group;");
    }

    for (int c = 0; c < NC; ++c) {
        if (c + 1 < NC) {
            const uint32_t d = dst0 + ((c + 1) & 1) * STAGEB;
            const size_t ao = arowoff + (size_t)(c + 1) * 32 + lch * 8;
            const size_t bo = browoff + (size_t)(c + 1) * 32 + lch * 8;
            cp16(d,            Ah + ao, 16); cp16(d + 16,           Ah + ao + 8, 16);
            cp16(d + MATB,     Al + ao, 16); cp16(d + MATB + 16,    Al + ao + 8, 16);
            cp16(d + 2*MATB,   Bh + bo, bok); cp16(d + 2*MATB + 16, Bh + bo + 8, bok);
            cp16(d + 3*MATB,   Bl + bo, bok); cp16(d + 3*MATB + 16, Bl + bo + 8, bok);
            asm volatile("cp.async.commit_group;");
            asm volatile("cp.async.wait_group 1;");
        } else {
            asm volatile("cp.async.wait_group 0;");
        }
        __syncthreads();

        const uint32_t st = sb + (c & 1) * STAGEB;
#pragma unroll
        for (int ks = 0; ks < 2; ++ks) {
            uint32_t ah[4][4], al[4][4], bh[4][2], bl[4][2];
            // A fragments: lanes 0-15 -> rows, lanes 16-31 -> +1 k-chunk
            const int arow = wr * 64 + (lid & 15);
            const int akc  = ks * 2 + (lid >> 4);
#pragma unroll
            for (int mt = 0; mt < 4; ++mt) {
                const uint32_t a = st + (arow + mt * 16) * ROWB + akc * 16;
                ldmatrix_x4(ah[mt], a);
                ldmatrix_x4(al[mt], a + MATB);
            }
            // B fragments: lanes 0-7 rows k0-7, lanes 8-15 rows k8-15
            const int brow = wc * 32 + (lid & 7);
            const int bkc  = ks * 2 + ((lid >> 3) & 1);
#pragma unroll
            for (int nt = 0; nt < 4; ++nt) {
                const uint32_t b = st + 2*MATB + (brow + nt * 8) * ROWB + bkc * 16;
                ldmatrix_x2(bh[nt], b);
                ldmatrix_x2(bl[nt], b + MATB);
            }
#pragma unroll
            for (int mt = 0; mt < 4; ++mt)
#pragma unroll
                for (int nt = 0; nt < 4; ++nt) {
                    mma_bf16(acc[mt][nt], ah[mt], bh[nt]);
                    mma_bf16(acc[mt][nt], ah[mt], bl[nt]);
                    mma_bf16(acc[mt][nt], al[mt], bh[nt]);
                }
        }
        __syncthreads();
    }

    // epilogue: fragment -> global (float2 pairs; N is even)
    const int mbase = bm + wr * 64 + (lid >> 2);
    const int nbase = bn + wc * 32 + (lid & 3) * 2;
#pragma unroll
    for (int mt = 0; mt < 4; ++mt) {
#pragma unroll
        for (int nt = 0; nt < 4; ++nt) {
            const int n0 = nbase + nt * 8;
            if (n0 < N) {
                const int m0 = mbase + mt * 16;
                float2 v0 = make_float2(acc[mt][nt][0], acc[mt][nt][1]);
                float2 v1 = make_float2(acc[mt][nt][2], acc[mt][nt][3]);
                *(float2*)(C + (size_t)m0 * N + n0)       = v0;
                *(float2*)(C + (size_t)(m0 + 8) * N + n0) = v1;
            }
        }
    }
}

// ---------------------------------------------------------------------------
// fp32 -> bf16 hi/lo split
// ---------------------------------------------------------------------------
__global__ void split_kernel(const float* __restrict__ src,
                             __nv_bfloat16* __restrict__ hi,
                             __nv_bfloat16* __restrict__ lo, int n)
{
    const int i = blockIdx.x * 256 + threadIdx.x;
    if (i >= n) return;
    const float x = src[i];
    const __nv_bfloat16 h = __float2bfloat16(x);
    hi[i] = h;
    lo[i] = __float2bfloat16(x - __bfloat162float(h));
}

// ---------------------------------------------------------------------------
// Depthwise causal conv (width 4) + bias + SiLU over the xBC slice of g_zx.
// ---------------------------------------------------------------------------
__global__ void conv_silu_kernel(const float* __restrict__ cw,
                                 const float* __restrict__ cb)
{
    const int idx = blockIdx.x * 256 + threadIdx.x;
    if (idx >= NTOK * CONVDIM) return;
    const int c  = idx % CONVDIM;
    const int bt = idx / CONVDIM;
    const int t  = bt % SEQLEN;
    float acc = cb[c];
#pragma unroll
    for (int k = 0; k < 4; k++) {
        const int tt = t - 3 + k;
        if (tt >= 0)
            acc = fmaf(cw[c * 4 + k],
                       g_zx[((size_t)bt + k - 3) * DINPROJ + DINNER + c], acc);
    }
    g_conv[idx] = acc / (1.f + expf(-acc));   // silu
}

// ---------------------------------------------------------------------------
// dt_dis = softplus(dt + dt_bias); dA = exp(dt_dis * (-exp(A_log)))
// ---------------------------------------------------------------------------
__global__ void dt_kernel(const float* __restrict__ dt_bias,
                          const float* __restrict__ A_log)
{
    const int idx = blockIdx.x * 256 + threadIdx.x;
    if (idx >= NTOK * NHEADS) return;
    const int h  = idx % NHEADS;
    const int bt = idx / NHEADS;
    const float x  = g_zx[(size_t)bt * DINPROJ + DINNER + CONVDIM + h] + dt_bias[h];
    const float sp = (x > 20.f) ? x : log1pf(expf(x));
    const float Ah = -expf(A_log[h]);
    g_dt[idx] = sp;
    g_dA[idx] = expf(sp * Ah);
}

__global__ void zero_y_kernel()
{
    const int idx = blockIdx.x * 256 + threadIdx.x;
    if (idx < NTOK * DINNER) g_y[idx] = 0.f;
}

// ---------------------------------------------------------------------------
// Selective scan. grid = (4 n-slices, NHEADS, BATCH), 256 threads.
// thread (p = tid>>2, q = tid&3) owns state[p, nb..nb+8) in registers.
// ---------------------------------------------------------------------------
__global__ __launch_bounds__(256) void scan_kernel()
{
    const int g4 = blockIdx.x, h = blockIdx.y, b = blockIdx.z;
    const int tid = threadIdx.x;
    const int p = tid >> 2, q = tid & 3;
    const int nb = g4 * 32 + q * 8;

    const float* rowbase = g_conv + (size_t)b * SEQLEN * CONVDIM;
    const float* dtp = g_dt + (size_t)b * SEQLEN * NHEADS + h;
    const float* dAp = g_dA + (size_t)b * SEQLEN * NHEADS + h;
    float* yout = g_y + (size_t)b * SEQLEN * DINNER + h * HEADDIM + p;

    float s[8];
#pragma unroll
    for (int i = 0; i < 8; i++) s[i] = 0.f;

    const float* r0 = rowbase;
    float4 nB0 = *(const float4*)(r0 + DINNER + nb);
    float4 nB1 = *(const float4*)(r0 + DINNER + nb + 4);
    float4 nC0 = *(const float4*)(r0 + DINNER + DSTATE + nb);
    float4 nC1 = *(const float4*)(r0 + DINNER + DSTATE + nb + 4);
    float nx  = r0[h * HEADDIM + p];
    float ndt = dtp[0];
    float ndA = dAp[0];

    for (int t = 0; t < SEQLEN; ++t) {
        const float4 B0 = nB0, B1 = nB1, C0 = nC0, C1 = nC1;
        const float xv = nx, dtv = ndt, dAv = ndA;
        if (t + 1 < SEQLEN) {
            const float* r = rowbase + (size_t)(t + 1) * CONVDIM;
            nB0 = *(const float4*)(r + DINNER + nb);
            nB1 = *(const float4*)(r + DINNER + nb + 4);
            nC0 = *(const float4*)(r + DINNER + DSTATE + nb);
            nC1 = *(const float4*)(r + DINNER + DSTATE + nb + 4);
            nx  = r[h * HEADDIM + p];
            ndt = dtp[(size_t)(t + 1) * NHEADS];
            ndA = dAp[(size_t)(t + 1) * NHEADS];
        }
        const float coef = dtv * xv;
        float acc;
        s[0] = fmaf(s[0], dAv, coef * B0.x); acc = s[0] * C0.x;
        s[1] = fmaf(s[1], dAv, coef * B0.y); acc = fmaf(s[1], C0.y, acc);
        s[2] = fmaf(s[2], dAv, coef * B0.z); acc = fmaf(s[2], C0.z, acc);
        s[3] = fmaf(s[3], dAv, coef * B0.w); acc = fmaf(s[3], C0.w, acc);
        s[4] = fmaf(s[4], dAv, coef * B1.x); acc = fmaf(s[4], C1.x, acc);
        s[5] = fmaf(s[5], dAv, coef * B1.y); acc = fmaf(s[5], C1.y, acc);
        s[6] = fmaf(s[6], dAv, coef * B1.z); acc = fmaf(s[6], C1.z, acc);
        s[7] = fmaf(s[7], dAv, coef * B1.w); acc = fmaf(s[7], C1.w, acc);
        acc += __shfl_xor_sync(0xffffffffu, acc, 1);
        acc += __shfl_xor_sync(0xffffffffu, acc, 2);
        if (q == 0) atomicAdd(yout + (size_t)t * DINNER, acc);
    }
}

// ---------------------------------------------------------------------------
// y += x*D; yz = y*silu(z); RMSNorm(yz) * norm_w  -> bf16 hi/lo (GEMM2 input)
// ---------------------------------------------------------------------------
__global__ __launch_bounds__(256) void gate_norm_kernel(
    const float* __restrict__ Dv, const float* __restrict__ nw)
{
    const int bt = blockIdx.x;
    const float* zrow = g_zx   + (size_t)bt * DINPROJ;
    const float* xrow = g_conv + (size_t)bt * CONVDIM;
    const float* yrow = g_y    + (size_t)bt * DINNER;

    float v[6];
    float ss = 0.f;
#pragma unroll
    for (int i = 0; i < 6; i++) {
        const int c = threadIdx.x + i * 256;
        const float yv = fmaf(xrow[c], Dv[c >> 6], yrow[c]);
        const float z  = zrow[c];
        const float gz = z / (1.f + expf(-z));
        const float val = yv * gz;
        v[i] = val;
        ss = fmaf(val, val, ss);
    }
#pragma unroll
    for (int o = 16; o; o >>= 1) ss += __shfl_xor_sync(0xffffffffu, ss, o);
    __shared__ float sred[8];
    if ((threadIdx.x & 31) == 0) sred[threadIdx.x >> 5] = ss;
    __syncthreads();
    float tot = 0.f;
#pragma unroll
    for (int i = 0; i < 8; i++) tot += sred[i];
    const float scale = rsqrtf(tot * (1.f / DINNER) + 1e-5f);

    __nv_bfloat16* yh = g_yn_hi + (size_t)bt * DINNER;
    __nv_bfloat16* yl = g_yn_lo + (size_t)bt * DINNER;
#pragma unroll
    for (int i = 0; i < 6; i++) {
        const int c = threadIdx.x + i * 256;
        const float val = v[i] * scale * nw[c];
        const __nv_bfloat16 h = __float2bfloat16(val);
        yh[c] = h;
        yl[c] = __float2bfloat16(val - __bfloat162float(h));
    }
}

// ---------------------------------------------------------------------------
// Launch
// ---------------------------------------------------------------------------
extern "C" void kernel_launch(void* const* d_in, const int* in_sizes, int n_in,
                              void* d_out, int out_size)
{
    const float* u          = (const float*)d_in[0];
    const float* in_proj_w  = (const float*)d_in[1];
    const float* conv_w     = (const float*)d_in[2];
    const float* conv_b     = (const float*)d_in[3];
    const float* dt_bias    = (const float*)d_in[4];
    const float* A_log      = (const float*)d_in[5];
    const float* Dv         = (const float*)d_in[6];
    const float* norm_w     = (const float*)d_in[7];
    const float* out_proj_w = (const float*)d_in[8];
    float* out = (float*)d_out;

    float* zx = nullptr;
    __nv_bfloat16 *uh, *ul, *w1h, *w1l, *w2h, *w2l, *ynh, *ynl;
    cudaGetSymbolAddress((void**)&zx,  g_zx);
    cudaGetSymbolAddress((void**)&uh,  g_u_hi);
    cudaGetSymbolAddress((void**)&ul,  g_u_lo);
    cudaGetSymbolAddress((void**)&w1h, g_w1_hi);
    cudaGetSymbolAddress((void**)&w1l, g_w1_lo);
    cudaGetSymbolAddress((void**)&w2h, g_w2_hi);
    cudaGetSymbolAddress((void**)&w2l, g_w2_lo);
    cudaGetSymbolAddress((void**)&ynh, g_yn_hi);
    cudaGetSymbolAddress((void**)&ynl, g_yn_lo);

    cudaFuncSetAttribute(gemm_mma,
                         cudaFuncAttributeMaxDynamicSharedMemorySize, GEMM_SMEM);

    // 0) bf16 hi/lo splits for GEMM operands
    split_kernel<<<(NTOK * DMODEL + 255) / 256, 256>>>(u, uh, ul, NTOK * DMODEL);
    split_kernel<<<(DINPROJ * DMODEL + 255) / 256, 256>>>(in_proj_w, w1h, w1l,
                                                          DINPROJ * DMODEL);
    split_kernel<<<(DMODEL * DINNER + 255) / 256, 256>>>(out_proj_w, w2h, w2l,
                                                         DMODEL * DINNER);

    // 1) zxbcdt = u @ in_proj_w^T   (4096 x 3352, K=768) — HMMA bf16x3
    dim3 g1((DINPROJ + 127) / 128, NTOK / 128);
    gemm_mma<<<g1, 256, GEMM_SMEM>>>(uh, ul, w1h, w1l, zx,
                                     NTOK, DINPROJ, DMODEL);

    // 2) depthwise causal conv + silu on xBC slice
    conv_silu_kernel<<<(NTOK * CONVDIM + 255) / 256, 256>>>(conv_w, conv_b);

    // 3) dt softplus / dA
    dt_kernel<<<(NTOK * NHEADS + 255) / 256, 256>>>(dt_bias, A_log);

    // 4) zero scan accumulator
    zero_y_kernel<<<(NTOK * DINNER + 255) / 256, 256>>>();

    // 5) selective scan
    scan_kernel<<<dim3(4, NHEADS, BATCH), 256>>>();

    // 6) gate + RMSNorm -> bf16 hi/lo
    gate_norm_kernel<<<NTOK, 256>>>(Dv, norm_w);

    // 7) out = yn @ out_proj_w^T   (4096 x 768, K=1536) — HMMA bf16x3
    dim3 g2((DMODEL + 127) / 128, NTOK / 128);
    gemm_mma<<<g2, 256, GEMM_SMEM>>>(ynh, ynl, w2h, w2l, out,
                                     NTOK, DMODEL, DINNER);
}

// round 4
// speedup vs baseline: 1.7653x; 1.1286x over previous
#include <cuda_runtime.h>
#include <cuda_bf16.h>
#include <math.h>
#include <stdint.h>

#define BATCH   2
#define SEQLEN  2048
#define NTOK    (BATCH*SEQLEN)        // 4096
#define DMODEL  768
#define DINNER  1536
#define DSTATE  128
#define HEADDIM 64
#define NHEADS  24
#define CONVDIM 1792                  // DINNER + 2*DSTATE
#define DINPROJ 3352                  // 2*DINNER + 2*DSTATE + NHEADS

// ---------------------------------------------------------------------------
// Scratch buffers (device globals — no allocations allowed)
// ---------------------------------------------------------------------------
__device__ __align__(128) float g_zx[NTOK * DINPROJ];     // in_proj output
__device__ __align__(128) float g_conv[NTOK * CONVDIM];   // conv+silu output (x | B | C)
__device__ __align__(128) float g_dt[NTOK * NHEADS];      // softplus(dt + bias)
__device__ __align__(128) float g_dA[NTOK * NHEADS];      // exp(dt * A)
__device__ __align__(128) float g_y[NTOK * DINNER];       // scan output (atomics)

// bf16 hi/lo split operands for tensor-core GEMMs
__device__ __align__(128) __nv_bfloat16 g_u_hi[NTOK * DMODEL];
__device__ __align__(128) __nv_bfloat16 g_u_lo[NTOK * DMODEL];
__device__ __align__(128) __nv_bfloat16 g_w1_hi[DINPROJ * DMODEL];
__device__ __align__(128) __nv_bfloat16 g_w1_lo[DINPROJ * DMODEL];
__device__ __align__(128) __nv_bfloat16 g_w2_hi[DMODEL * DINNER];
__device__ __align__(128) __nv_bfloat16 g_w2_lo[DMODEL * DINNER];
__device__ __align__(128) __nv_bfloat16 g_yn_hi[NTOK * DINNER];
__device__ __align__(128) __nv_bfloat16 g_yn_lo[NTOK * DINNER];

// ---------------------------------------------------------------------------
// MMA helpers (baseline PTX — works under compute_103 virtual arch)
// ---------------------------------------------------------------------------
static __device__ __forceinline__ uint32_t smem_u32(const void* p) {
    return (uint32_t)__cvta_generic_to_shared(p);
}

static __device__ __forceinline__ void mma_bf16(
    float* d, const uint32_t* a, const uint32_t* b)
{
    asm volatile(
        "mma.sync.aligned.m16n8k16.row.col.f32.bf16.bf16.f32 "
        "{%0,%1,%2,%3}, {%4,%5,%6,%7}, {%8,%9}, {%0,%1,%2,%3};"
        : "+f"(d[0]), "+f"(d[1]), "+f"(d[2]), "+f"(d[3])
        : "r"(a[0]), "r"(a[1]), "r"(a[2]), "r"(a[3]), "r"(b[0]), "r"(b[1]));
}

static __device__ __forceinline__ void ldmatrix_x4(uint32_t* r, uint32_t addr)
{
    asm volatile("ldmatrix.sync.aligned.m8n8.x4.shared.b16 {%0,%1,%2,%3}, [%4];"
                 : "=r"(r[0]), "=r"(r[1]), "=r"(r[2]), "=r"(r[3]) : "r"(addr));
}

static __device__ __forceinline__ void ldmatrix_x2(uint32_t* r, uint32_t addr)
{
    asm volatile("ldmatrix.sync.aligned.m8n8.x2.shared.b16 {%0,%1}, [%2];"
                 : "=r"(r[0]), "=r"(r[1]) : "r"(addr));
}

static __device__ __forceinline__ void cp16(uint32_t dst, const void* src, int sz)
{
    asm volatile("cp.async.cg.shared.global [%0], [%1], 16, %2;"
                 :: "r"(dst), "l"(src), "r"(sz));
}

// ---------------------------------------------------------------------------
// bf16x3 GEMM via mma.sync:  C[M,N] = A[M,K] @ B[N,K]^T  (~fp32 accuracy)
// CTA tile 128x128, BK=32, 8 warps (2x4), warp tile 64x32.
// Double-buffered cp.async staging; 80B-padded rows -> conflict-free ldmatrix.
// M % 128 == 0, K % 32 == 0; N guarded.
// ---------------------------------------------------------------------------
#define ROWB   80                         // padded row stride (32 bf16 -> 80B)
#define MATB   (128 * ROWB)               // 10240 per matrix
#define STAGEB (4 * MATB)                 // Ah | Al | Bh | Bl  = 40960
#define GEMM_SMEM (2 * STAGEB)            // 81920

__global__ void __launch_bounds__(256) gemm_mma(
    const __nv_bfloat16* __restrict__ Ah, const __nv_bfloat16* __restrict__ Al,
    const __nv_bfloat16* __restrict__ Bh, const __nv_bfloat16* __restrict__ Bl,
    float* __restrict__ C, int M, int N, int K)
{
    extern __shared__ __align__(128) char smem[];
    const uint32_t sb = smem_u32(smem);
    const int tid = threadIdx.x;
    const int wid = tid >> 5, lid = tid & 31;
    const int bm = blockIdx.y * 128;
    const int bn = blockIdx.x * 128;
    const int wr = wid & 1;               // warp m-row (x64)
    const int wc = wid >> 1;              // warp n-col (x32)

    float acc[4][4][4];
#pragma unroll
    for (int i = 0; i < 4; i++)
#pragma unroll
        for (int j = 0; j < 4; j++)
#pragma unroll
            for (int k = 0; k < 4; k++) acc[i][j][k] = 0.f;

    // staging: thread -> (row = tid>>1, two 16B chunks at (tid&1)*2)
    const int lrow = tid >> 1;
    const int lch  = (tid & 1) * 2;
    const int bok  = (bn + lrow) < N ? 16 : 0;
    const size_t arowoff = (size_t)(bm + lrow) * K;
    const size_t browoff = (size_t)(bok ? (bn + lrow) : 0) * K;
    const uint32_t dst0 = sb + lrow * ROWB + lch * 16;

    const int NC = K >> 5;

    // prologue: stage chunk 0 into stage 0
    {
        const size_t ao = arowoff + lch * 8;
        const size_t bo = browoff + lch * 8;
        cp16(dst0,             Ah + ao, 16); cp16(dst0 + 16,            Ah + ao + 8, 16);
        cp16(dst0 + MATB,      Al + ao, 16); cp16(dst0 + MATB + 16,     Al + ao + 8, 16);
        cp16(dst0 + 2*MATB,    Bh + bo, bok); cp16(dst0 + 2*MATB + 16,  Bh + bo + 8, bok);
        cp16(dst0 + 3*MATB,    Bl + bo, bok); cp16(dst0 + 3*MATB + 16,  Bl + bo + 8, bok);
        asm volatile("cp.async.commit_group;");
    }

    for (int c = 0; c < NC; ++c) {
        if (c + 1 < NC) {
            const uint32_t d = dst0 + ((c + 1) & 1) * STAGEB;
            const size_t ao = arowoff + (size_t)(c + 1) * 32 + lch * 8;
            const size_t bo = browoff + (size_t)(c + 1) * 32 + lch * 8;
            cp16(d,            Ah + ao, 16); cp16(d + 16,           Ah + ao + 8, 16);
            cp16(d + MATB,     Al + ao, 16); cp16(d + MATB + 16,    Al + ao + 8, 16);
            cp16(d + 2*MATB,   Bh + bo, bok); cp16(d + 2*MATB + 16, Bh + bo + 8, bok);
            cp16(d + 3*MATB,   Bl + bo, bok); cp16(d + 3*MATB + 16, Bl + bo + 8, bok);
            asm volatile("cp.async.commit_group;");
            asm volatile("cp.async.wait_group 1;");
        } else {
            asm volatile("cp.async.wait_group 0;");
        }
        __syncthreads();

        const uint32_t st = sb + (c & 1) * STAGEB;
#pragma unroll
        for (int ks = 0; ks < 2; ++ks) {
            uint32_t ah[4][4], al[4][4], bh[4][2], bl[4][2];
            const int arow = wr * 64 + (lid & 15);
            const int akc  = ks * 2 + (lid >> 4);
#pragma unroll
            for (int mt = 0; mt < 4; ++mt) {
                const uint32_t a = st + (arow + mt * 16) * ROWB + akc * 16;
                ldmatrix_x4(ah[mt], a);
                ldmatrix_x4(al[mt], a + MATB);
            }
            const int brow = wc * 32 + (lid & 7);
            const int bkc  = ks * 2 + ((lid >> 3) & 1);
#pragma unroll
            for (int nt = 0; nt < 4; ++nt) {
                const uint32_t b = st + 2*MATB + (brow + nt * 8) * ROWB + bkc * 16;
                ldmatrix_x2(bh[nt], b);
                ldmatrix_x2(bl[nt], b + MATB);
            }
#pragma unroll
            for (int mt = 0; mt < 4; ++mt)
#pragma unroll
                for (int nt = 0; nt < 4; ++nt) {
                    mma_bf16(acc[mt][nt], ah[mt], bh[nt]);
                    mma_bf16(acc[mt][nt], ah[mt], bl[nt]);
                    mma_bf16(acc[mt][nt], al[mt], bh[nt]);
                }
        }
        __syncthreads();
    }

    // epilogue: fragment -> global (float2 pairs; N is even)
    const int mbase = bm + wr * 64 + (lid >> 2);
    const int nbase = bn + wc * 32 + (lid & 3) * 2;
#pragma unroll
    for (int mt = 0; mt < 4; ++mt) {
#pragma unroll
        for (int nt = 0; nt < 4; ++nt) {
            const int n0 = nbase + nt * 8;
            if (n0 < N) {
                const int m0 = mbase + mt * 16;
                float2 v0 = make_float2(acc[mt][nt][0], acc[mt][nt][1]);
                float2 v1 = make_float2(acc[mt][nt][2], acc[mt][nt][3]);
                *(float2*)(C + (size_t)m0 * N + n0)       = v0;
                *(float2*)(C + (size_t)(m0 + 8) * N + n0) = v1;
            }
        }
    }
}

// ---------------------------------------------------------------------------
// fp32 -> bf16 hi/lo split
// ---------------------------------------------------------------------------
__global__ void split_kernel(const float* __restrict__ src,
                             __nv_bfloat16* __restrict__ hi,
                             __nv_bfloat16* __restrict__ lo, int n)
{
    const int i = blockIdx.x * 256 + threadIdx.x;
    if (i >= n) return;
    const float x = src[i];
    const __nv_bfloat16 h = __float2bfloat16(x);
    hi[i] = h;
    lo[i] = __float2bfloat16(x - __bfloat162float(h));
}

// ---------------------------------------------------------------------------
// Depthwise causal conv (width 4) + bias + SiLU over the xBC slice of g_zx.
// ---------------------------------------------------------------------------
__global__ void conv_silu_kernel(const float* __restrict__ cw,
                                 const float* __restrict__ cb)
{
    const int idx = blockIdx.x * 256 + threadIdx.x;
    if (idx >= NTOK * CONVDIM) return;
    const int c  = idx % CONVDIM;
    const int bt = idx / CONVDIM;
    const int t  = bt % SEQLEN;
    float acc = cb[c];
#pragma unroll
    for (int k = 0; k < 4; k++) {
        const int tt = t - 3 + k;
        if (tt >= 0)
            acc = fmaf(cw[c * 4 + k],
                       g_zx[((size_t)bt + k - 3) * DINPROJ + DINNER + c], acc);
    }
    g_conv[idx] = acc / (1.f + __expf(-acc));   // silu (fast exp: no compounding)
}

// ---------------------------------------------------------------------------
// dt_dis = softplus(dt + dt_bias); dA = exp(dt_dis * (-exp(A_log)))
// (precise expf here: dA errors compound multiplicatively over the scan)
// ---------------------------------------------------------------------------
__global__ void dt_kernel(const float* __restrict__ dt_bias,
                          const float* __restrict__ A_log)
{
    const int idx = blockIdx.x * 256 + threadIdx.x;
    if (idx >= NTOK * NHEADS) return;
    const int h  = idx % NHEADS;
    const int bt = idx / NHEADS;
    const float x  = g_zx[(size_t)bt * DINPROJ + DINNER + CONVDIM + h] + dt_bias[h];
    const float sp = (x > 20.f) ? x : log1pf(expf(x));
    const float Ah = -expf(A_log[h]);
    g_dt[idx] = sp;
    g_dA[idx] = expf(sp * Ah);
}

__global__ void zero_y_kernel()
{
    const int idx = blockIdx.x * 256 + threadIdx.x;
    if (idx < NTOK * DINNER) g_y[idx] = 0.f;
}

// ---------------------------------------------------------------------------
// Selective scan with 4-deep register prefetch pipeline.
// grid = (4 n-slices, NHEADS, BATCH), 256 threads.
// thread (p = tid>>2, q = tid&3) owns state[p, nb..nb+8) in registers.
// Loads for step t+4 are issued while computing step t -> L2 latency hidden.
// ---------------------------------------------------------------------------
#define PF 4

__global__ __launch_bounds__(256) void scan_kernel()
{
    const int g4 = blockIdx.x, h = blockIdx.y, b = blockIdx.z;
    const int tid = threadIdx.x;
    const int p = tid >> 2, q = tid & 3;
    const int nb = g4 * 32 + q * 8;

    const float* rowbase = g_conv + (size_t)b * SEQLEN * CONVDIM;
    const float* dtp = g_dt + (size_t)b * SEQLEN * NHEADS + h;
    const float* dAp = g_dA + (size_t)b * SEQLEN * NHEADS + h;
    float* yout = g_y + (size_t)b * SEQLEN * DINNER + h * HEADDIM + p;

    const int xoff = h * HEADDIM + p;

    float s[8];
#pragma unroll
    for (int i = 0; i < 8; i++) s[i] = 0.f;

    float4 pB0[PF], pB1[PF], pC0[PF], pC1[PF];
    float  px[PF], pdt[PF], pdA[PF];
#pragma unroll
    for (int i = 0; i < PF; i++) {
        const float* r = rowbase + (size_t)i * CONVDIM;
        pB0[i] = *(const float4*)(r + DINNER + nb);
        pB1[i] = *(const float4*)(r + DINNER + nb + 4);
        pC0[i] = *(const float4*)(r + DINNER + DSTATE + nb);
        pC1[i] = *(const float4*)(r + DINNER + DSTATE + nb + 4);
        px[i]  = r[xoff];
        pdt[i] = dtp[(size_t)i * NHEADS];
        pdA[i] = dAp[(size_t)i * NHEADS];
    }

    for (int t = 0; t < SEQLEN; t += PF) {
#pragma unroll
        for (int j = 0; j < PF; j++) {
            const float4 B0 = pB0[j], B1 = pB1[j], C0 = pC0[j], C1 = pC1[j];
            const float xv = px[j], dtv = pdt[j], dAv = pdA[j];

            const int tn = t + j + PF;
            if (tn < SEQLEN) {
                const float* r = rowbase + (size_t)tn * CONVDIM;
                pB0[j] = *(const float4*)(r + DINNER + nb);
                pB1[j] = *(const float4*)(r + DINNER + nb + 4);
                pC0[j] = *(const float4*)(r + DINNER + DSTATE + nb);
                pC1[j] = *(const float4*)(r + DINNER + DSTATE + nb + 4);
                px[j]  = r[xoff];
                pdt[j] = dtp[(size_t)tn * NHEADS];
                pdA[j] = dAp[(size_t)tn * NHEADS];
            }

            const float coef = dtv * xv;
            float acc;
            s[0] = fmaf(s[0], dAv, coef * B0.x); acc = s[0] * C0.x;
            s[1] = fmaf(s[1], dAv, coef * B0.y); acc = fmaf(s[1], C0.y, acc);
            s[2] = fmaf(s[2], dAv, coef * B0.z); acc = fmaf(s[2], C0.z, acc);
            s[3] = fmaf(s[3], dAv, coef * B0.w); acc = fmaf(s[3], C0.w, acc);
            s[4] = fmaf(s[4], dAv, coef * B1.x); acc = fmaf(s[4], C1.x, acc);
            s[5] = fmaf(s[5], dAv, coef * B1.y); acc = fmaf(s[5], C1.y, acc);
            s[6] = fmaf(s[6], dAv, coef * B1.z); acc = fmaf(s[6], C1.z, acc);
            s[7] = fmaf(s[7], dAv, coef * B1.w); acc = fmaf(s[7], C1.w, acc);
            acc += __shfl_xor_sync(0xffffffffu, acc, 1);
            acc += __shfl_xor_sync(0xffffffffu, acc, 2);
            if (q == 0) atomicAdd(yout + (size_t)(t + j) * DINNER, acc);
        }
    }
}

// ---------------------------------------------------------------------------
// y += x*D; yz = y*silu(z); RMSNorm(yz) * norm_w  -> bf16 hi/lo (GEMM2 input)
// ---------------------------------------------------------------------------
__global__ __launch_bounds__(256) void gate_norm_kernel(
    const float* __restrict__ Dv, const float* __restrict__ nw)
{
    const int bt = blockIdx.x;
    const float* zrow = g_zx   + (size_t)bt * DINPROJ;
    const float* xrow = g_conv + (size_t)bt * CONVDIM;
    const float* yrow = g_y    + (size_t)bt * DINNER;

    float v[6];
    float ss = 0.f;
#pragma unroll
    for (int i = 0; i < 6; i++) {
        const int c = threadIdx.x + i * 256;
        const float yv = fmaf(xrow[c], Dv[c >> 6], yrow[c]);
        const float z  = zrow[c];
        const float gz = z / (1.f + __expf(-z));
        const float val = yv * gz;
        v[i] = val;
        ss = fmaf(val, val, ss);
    }
#pragma unroll
    for (int o = 16; o; o >>= 1) ss += __shfl_xor_sync(0xffffffffu, ss, o);
    __shared__ float sred[8];
    if ((threadIdx.x & 31) == 0) sred[threadIdx.x >> 5] = ss;
    __syncthreads();
    float tot = 0.f;
#pragma unroll
    for (int i = 0; i < 8; i++) tot += sred[i];
    const float scale = rsqrtf(tot * (1.f / DINNER) + 1e-5f);

    __nv_bfloat16* yh = g_yn_hi + (size_t)bt * DINNER;
    __nv_bfloat16* yl = g_yn_lo + (size_t)bt * DINNER;
#pragma unroll
    for (int i = 0; i < 6; i++) {
        const int c = threadIdx.x + i * 256;
        const float val = v[i] * scale * nw[c];
        const __nv_bfloat16 h = __float2bfloat16(val);
        yh[c] = h;
        yl[c] = __float2bfloat16(val - __bfloat162float(h));
    }
}

// ---------------------------------------------------------------------------
// Launch
// ---------------------------------------------------------------------------
extern "C" void kernel_launch(void* const* d_in, const int* in_sizes, int n_in,
                              void* d_out, int out_size)
{
    const float* u          = (const float*)d_in[0];
    const float* in_proj_w  = (const float*)d_in[1];
    const float* conv_w     = (const float*)d_in[2];
    const float* conv_b     = (const float*)d_in[3];
    const float* dt_bias    = (const float*)d_in[4];
    const float* A_log      = (const float*)d_in[5];
    const float* Dv         = (const float*)d_in[6];
    const float* norm_w     = (const float*)d_in[7];
    const float* out_proj_w = (const float*)d_in[8];
    float* out = (float*)d_out;

    float* zx = nullptr;
    __nv_bfloat16 *uh, *ul, *w1h, *w1l, *w2h, *w2l, *ynh, *ynl;
    cudaGetSymbolAddress((void**)&zx,  g_zx);
    cudaGetSymbolAddress((void**)&uh,  g_u_hi);
    cudaGetSymbolAddress((void**)&ul,  g_u_lo);
    cudaGetSymbolAddress((void**)&w1h, g_w1_hi);
    cudaGetSymbolAddress((void**)&w1l, g_w1_lo);
    cudaGetSymbolAddress((void**)&w2h, g_w2_hi);
    cudaGetSymbolAddress((void**)&w2l, g_w2_lo);
    cudaGetSymbolAddress((void**)&ynh, g_yn_hi);
    cudaGetSymbolAddress((void**)&ynl, g_yn_lo);

    cudaFuncSetAttribute(gemm_mma,
                         cudaFuncAttributeMaxDynamicSharedMemorySize, GEMM_SMEM);

    // 0) bf16 hi/lo splits for GEMM operands
    split_kernel<<<(NTOK * DMODEL + 255) / 256, 256>>>(u, uh, ul, NTOK * DMODEL);
    split_kernel<<<(DINPROJ * DMODEL + 255) / 256, 256>>>(in_proj_w, w1h, w1l,
                                                          DINPROJ * DMODEL);
    split_kernel<<<(DMODEL * DINNER + 255) / 256, 256>>>(out_proj_w, w2h, w2l,
                                                         DMODEL * DINNER);

    // 1) zxbcdt = u @ in_proj_w^T   (4096 x 3352, K=768) — HMMA bf16x3
    dim3 g1((DINPROJ + 127) / 128, NTOK / 128);
    gemm_mma<<<g1, 256, GEMM_SMEM>>>(uh, ul, w1h, w1l, zx,
                                     NTOK, DINPROJ, DMODEL);

    // 2) depthwise causal conv + silu on xBC slice
    conv_silu_kernel<<<(NTOK * CONVDIM + 255) / 256, 256>>>(conv_w, conv_b);

    // 3) dt softplus / dA
    dt_kernel<<<(NTOK * NHEADS + 255) / 256, 256>>>(dt_bias, A_log);

    // 4) zero scan accumulator
    zero_y_kernel<<<(NTOK * DINNER + 255) / 256, 256>>>();

    // 5) selective scan (4-deep prefetch)
    scan_kernel<<<dim3(4, NHEADS, BATCH), 256>>>();

    // 6) gate + RMSNorm -> bf16 hi/lo
    gate_norm_kernel<<<NTOK, 256>>>(Dv, norm_w);

    // 7) out = yn @ out_proj_w^T   (4096 x 768, K=1536) — HMMA bf16x3
    dim3 g2((DMODEL + 127) / 128, NTOK / 128);
    gemm_mma<<<g2, 256, GEMM_SMEM>>>(ynh, ynl, w2h, w2l, out,
                                     NTOK, DMODEL, DINNER);
}